// round 9
// baseline (speedup 1.0000x reference)
#include <cuda_runtime.h>
#include <cuda_bf16.h>

// SparseConv2d: N=32, IC=OC=256, H=W=56, K=3, pad 1, ~90% zero weights. fp32 exact.
// R8: 2 images per CTA, interleaved {img0,img1} float2 smem tiles, packed
// fma.rn.f32x2 -> one LDS.64 feeds 2 px-FMAs. Halves instructions/FMA and CTA
// count; smem byte traffic (the 640us crossbar floor) unchanged.

#define NI      32
#define CC      256
#define HW      56
#define TOC     16          // ocs per block = warps per block
#define NOT     16          // 256 / TOC
#define RT      8           // output rows per tile
#define NTILE   7           // 56 / RT
#define SMW2    68          // smem row stride in float2 units (68%16==4 -> conflict-free)
#define PADW    64
#define PADH    58
#define THREADS 512

#define SLICEF  (PADH*PADW)      // floats per (n,ic) padded slice = 3712
#define IMGSTRF (CC*SLICEF)      // float offset img0 -> img1 = 950272

// per-ic smem block (bytes):
//   [0, 5440)      input: 10 rows * 68 float2 * 8B (cols 0..59 written)
//   [5440, 5456)   cnt[16]
//   [5456, 6608)   int2 e[16*9]
#define CNT_OFF 5440
#define ENT_OFF 5456
#define ICB     6608
#define IN_UNITS 600             // 10 rows * 60 cols, one interleaved float2 each
#define MT_CHUNKS 73             // sizeof(GBucket)/16

struct __align__(16) GBucket {
    unsigned char cnt[TOC];     // taps per local oc
    int2 e[TOC * 9];            // fixed stride 9: {w bits, delta = kh*SMW2 + kw}
};
static_assert(sizeof(GBucket) == 1168, "GBucket size");
static_assert(ENT_OFF + sizeof(GBucket) - 16 == ICB, "layout");

__device__ __align__(16) float g_pad[(size_t)NI * CC * PADH * PADW]; // ~121.6 MB scratch
__device__ GBucket g_buckets[NOT * CC];                              // ~4.8 MB
__device__ int     g_fmt;

// ---------------------------------------------------------------------------
// Mask dtype detection (bool/u8 vs int32 vs float32) by byte pattern.
// ---------------------------------------------------------------------------
__global__ void detect_fmt_kernel(const unsigned char* __restrict__ m) {
    __shared__ int nz[4];
    if (threadIdx.x < 4) nz[threadIdx.x] = 0;
    __syncthreads();
    for (int i = threadIdx.x; i < 4096; i += blockDim.x)
        if (m[i]) atomicOr(&nz[i & 3], 1);
    __syncthreads();
    if (threadIdx.x == 0) {
        int f;
        if (nz[1] | nz[2] | nz[3]) f = nz[0] ? 0 : 2;
        else                       f = 1;
        g_fmt = f;
    }
}

// ---------------------------------------------------------------------------
// Build per-(oc_tile, ic) tap lists, fixed 9-slot stride per oc.
// delta is in float2 units: kh*SMW2 + kw.
// ---------------------------------------------------------------------------
__global__ void build_buckets_kernel(const float* __restrict__ w,
                                     const void*  __restrict__ mask) {
    int bi = blockIdx.x * blockDim.x + threadIdx.x;
    if (bi >= NOT * CC) return;
    int ot = bi >> 8;
    int ic = bi & (CC - 1);
    int fmt = g_fmt;
    GBucket& b = g_buckets[bi];
    for (int ol = 0; ol < TOC; ++ol) {
        int oc = ot * TOC + ol;
        int base = (oc * CC + ic) * 9;
        int cnum = 0;
        for (int t = 0; t < 9; ++t) {
            int widx = base + t;
            bool nzb;
            if (fmt == 0)      nzb = ((const unsigned char*)mask)[widx] != 0;
            else if (fmt == 1) nzb = ((const int*)mask)[widx] != 0;
            else               nzb = ((const float*)mask)[widx] != 0.0f;
            if (nzb) {
                b.e[ol * 9 + cnum] = make_int2(__float_as_int(w[widx]),
                                               (t / 3) * SMW2 + (t % 3));
                ++cnum;
            }
        }
        b.cnt[ol] = (unsigned char)cnum;
    }
}

// ---------------------------------------------------------------------------
// Pre-pad input to [N*IC][58][64] (row/col = input + 1, zeros at borders).
// ---------------------------------------------------------------------------
__global__ void prepad_kernel(const float* __restrict__ in) {
    size_t s = blockIdx.x;                 // n*CC + ic, 8192 slices
    const float* ip = in + s * (HW * HW);
    float* op = g_pad + s * (PADH * PADW);
    for (int idx = threadIdx.x; idx < PADH * PADW; idx += blockDim.x) {
        int r = idx >> 6;
        int c = idx & 63;
        int gy = r - 1, gx = c - 1;
        float v = 0.0f;
        if ((unsigned)gy < HW && (unsigned)gx < HW)
            v = ip[gy * HW + gx];
        op[idx] = v;
    }
}

// ---------------------------------------------------------------------------
// Main sparse conv, 2 images per CTA.
// Block = 16 warps; warp w owns oc = ot*16 + w over an 8x56 tile of BOTH images.
// Lane: q = lane>>2 (row), m = lane&3 (col phase); pixels cols m+4k, k=0..13.
// smem holds {img0,img1} interleaved per pixel -> per tap: 14 LDS.64 + 14 FFMA2.
// LDS.64 conflict-free: phase bank-pair = (4q+m) mod 16, all distinct.
// Staging: 1 ic/iter; thread jobs: input float2 (2x LDG.32) or metadata uint4,
// register-prefetched, double-buffered, ONE __syncthreads per iteration.
// ---------------------------------------------------------------------------
__global__ __launch_bounds__(THREADS, 2)
void sparse_conv_kernel(const float* __restrict__ bias,
                        float* __restrict__ out) {
    __shared__ __align__(16) unsigned char s_buf[2][ICB];

    const int tid  = threadIdx.x;
    const int wid  = tid >> 5;
    const int lane = tid & 31;
    const int ot   = blockIdx.x;       // fastest dim: 16 blocks share input in L2
    const int ty   = blockIdx.y;
    const int n0   = 2 * blockIdx.z;   // image pair
    const int row0 = ty * RT;
    const int oc   = ot * TOC + wid;

    // ---- staging job 1 (all threads): interleaved input float2, unit = tid
    int j1 = tid / 60, c1 = tid - 60 * j1;
    const float* s1 = g_pad + ((size_t)(n0 * CC) * PADH + row0 + j1) * PADW + c1;
    const int d1 = j1 * (SMW2 * 8) + c1 * 8;

    // ---- staging job 2: tid<88 -> input unit 512+tid; 88<=tid<161 -> metadata
    const int jobt = (tid < 88) ? 1 : (tid < 88 + MT_CHUNKS ? 2 : 0);
    const float* s2 = nullptr;
    const unsigned char* s2m = nullptr;
    int d2 = 0;
    if (jobt == 1) {
        int u = 512 + tid;
        int j2 = u / 60, c2 = u - 60 * j2;
        s2 = g_pad + ((size_t)(n0 * CC) * PADH + row0 + j2) * PADW + c2;
        d2 = j2 * (SMW2 * 8) + c2 * 8;
    } else if (jobt == 2) {
        s2m = (const unsigned char*)&g_buckets[ot * CC] + (tid - 88) * 16;
        d2 = CNT_OFF + (tid - 88) * 16;
    }

    // ---- accumulators: 14 packed f32x2 {img0, img1}
    const float bv = __ldg(&bias[oc]);
    const int bvi = __float_as_int(bv);
    unsigned long long acc[14];
#pragma unroll
    for (int k = 0; k < 14; ++k)
        asm("mov.b64 %0, {%1, %1};" : "=l"(acc[k]) : "r"(bvi));

    const int q = lane >> 2;
    const int m = lane & 3;
    const int rbase = q * SMW2 + m;

    // ---- prefetch first slice
    float a0 = __ldg(s1), a1 = __ldg(s1 + IMGSTRF);
    float b0 = 0.f, b1 = 0.f;
    uint4 mv = make_uint4(0, 0, 0, 0);
    if (jobt == 1)      { b0 = __ldg(s2); b1 = __ldg(s2 + IMGSTRF); }
    else if (jobt == 2) { mv = *(const uint4*)s2m; }

    for (int it = 0; it < CC; ++it) {
        unsigned char* buf = s_buf[it & 1];
        *(float2*)(buf + d1) = make_float2(a0, a1);
        if (jobt == 1)      *(float2*)(buf + d2) = make_float2(b0, b1);
        else if (jobt == 2) *(uint4*)(buf + d2)  = mv;

        if (it + 1 < CC) {                  // prefetch next ic (overlaps compute)
            s1 += SLICEF;
            a0 = __ldg(s1); a1 = __ldg(s1 + IMGSTRF);
            if (jobt == 1)      { s2 += SLICEF; b0 = __ldg(s2); b1 = __ldg(s2 + IMGSTRF); }
            else if (jobt == 2) { s2m += sizeof(GBucket); mv = *(const uint4*)s2m; }
        }
        __syncthreads();
        // single sync is safe: reads of buf[it&1] precede (in program order) the
        // sync at it+1, which precedes the next overwrite of this buffer at it+2.

        const unsigned char* blk = buf;
        const int cnt = blk[CNT_OFF + wid];                       // broadcast
        const int2* ep = (const int2*)(blk + ENT_OFF) + wid * 9;
        const float2* sp = (const float2*)blk + rbase;
        for (int t = 0; t < cnt; ++t) {
            int2 e = ep[t];                                       // broadcast
            unsigned long long w2;
            asm("mov.b64 %0, {%1, %1};" : "=l"(w2) : "r"(e.x));
            const float2* qp = sp + e.y;
#pragma unroll
            for (int k = 0; k < 14; ++k) {
                unsigned long long x = *(const unsigned long long*)(qp + 4 * k);
                asm("fma.rn.f32x2 %0, %1, %2, %0;" : "+l"(acc[k]) : "l"(x), "l"(w2));
            }
        }
    }

    const int gy = row0 + q;
    float* o0 = out + ((size_t)(n0 * CC + oc) * HW + gy) * HW + m;
    float* o1 = o0 + (size_t)CC * HW * HW;
#pragma unroll
    for (int k = 0; k < 14; ++k) {
        float2 f = *(float2*)&acc[k];
        o0[4 * k] = f.x;
        o1[4 * k] = f.y;
    }
}

// ---------------------------------------------------------------------------
extern "C" void kernel_launch(void* const* d_in, const int* in_sizes, int n_in,
                              void* d_out, int out_size) {
    const float* input  = (const float*)d_in[0];
    const float* weight = (const float*)d_in[1];
    const float* bias   = (const float*)d_in[2];
    const void*  mask   = d_in[3];
    float* out = (float*)d_out;

    detect_fmt_kernel<<<1, 256>>>((const unsigned char*)mask);
    build_buckets_kernel<<<16, 256>>>(weight, mask);
    prepad_kernel<<<NI * CC, 256>>>(input);
    sparse_conv_kernel<<<dim3(NOT, NTILE, NI / 2), THREADS>>>(bias, out);
}

// round 10
// speedup vs baseline: 1.0034x; 1.0034x over previous
#include <cuda_runtime.h>
#include <cuda_bf16.h>

// SparseConv2d: N=32, IC=OC=256, H=W=56, K=3, pad 1, ~90% zero weights. fp32 exact.
// R8: 2 images per CTA, interleaved {img0,img1} float2 smem tiles, packed
// fma.rn.f32x2 -> one LDS.64 feeds 2 px-FMAs. Halves instructions/FMA and CTA
// count; smem byte traffic (the 640us crossbar floor) unchanged.

#define NI      32
#define CC      256
#define HW      56
#define TOC     16          // ocs per block = warps per block
#define NOT     16          // 256 / TOC
#define RT      8           // output rows per tile
#define NTILE   7           // 56 / RT
#define SMW2    68          // smem row stride in float2 units (68%16==4 -> conflict-free)
#define PADW    64
#define PADH    58
#define THREADS 512

#define SLICEF  (PADH*PADW)      // floats per (n,ic) padded slice = 3712
#define IMGSTRF (CC*SLICEF)      // float offset img0 -> img1 = 950272

// per-ic smem block (bytes):
//   [0, 5440)      input: 10 rows * 68 float2 * 8B (cols 0..59 written)
//   [5440, 5456)   cnt[16]
//   [5456, 6608)   int2 e[16*9]
#define CNT_OFF 5440
#define ENT_OFF 5456
#define ICB     6608
#define IN_UNITS 600             // 10 rows * 60 cols, one interleaved float2 each
#define MT_CHUNKS 73             // sizeof(GBucket)/16

struct __align__(16) GBucket {
    unsigned char cnt[TOC];     // taps per local oc
    int2 e[TOC * 9];            // fixed stride 9: {w bits, delta = kh*SMW2 + kw}
};
static_assert(sizeof(GBucket) == 1168, "GBucket size");
static_assert(ENT_OFF + sizeof(GBucket) - 16 == ICB, "layout");

__device__ __align__(16) float g_pad[(size_t)NI * CC * PADH * PADW]; // ~121.6 MB scratch
__device__ GBucket g_buckets[NOT * CC];                              // ~4.8 MB
__device__ int     g_fmt;

// ---------------------------------------------------------------------------
// Mask dtype detection (bool/u8 vs int32 vs float32) by byte pattern.
// ---------------------------------------------------------------------------
__global__ void detect_fmt_kernel(const unsigned char* __restrict__ m) {
    __shared__ int nz[4];
    if (threadIdx.x < 4) nz[threadIdx.x] = 0;
    __syncthreads();
    for (int i = threadIdx.x; i < 4096; i += blockDim.x)
        if (m[i]) atomicOr(&nz[i & 3], 1);
    __syncthreads();
    if (threadIdx.x == 0) {
        int f;
        if (nz[1] | nz[2] | nz[3]) f = nz[0] ? 0 : 2;
        else                       f = 1;
        g_fmt = f;
    }
}

// ---------------------------------------------------------------------------
// Build per-(oc_tile, ic) tap lists, fixed 9-slot stride per oc.
// delta is in float2 units: kh*SMW2 + kw.
// ---------------------------------------------------------------------------
__global__ void build_buckets_kernel(const float* __restrict__ w,
                                     const void*  __restrict__ mask) {
    int bi = blockIdx.x * blockDim.x + threadIdx.x;
    if (bi >= NOT * CC) return;
    int ot = bi >> 8;
    int ic = bi & (CC - 1);
    int fmt = g_fmt;
    GBucket& b = g_buckets[bi];
    for (int ol = 0; ol < TOC; ++ol) {
        int oc = ot * TOC + ol;
        int base = (oc * CC + ic) * 9;
        int cnum = 0;
        for (int t = 0; t < 9; ++t) {
            int widx = base + t;
            bool nzb;
            if (fmt == 0)      nzb = ((const unsigned char*)mask)[widx] != 0;
            else if (fmt == 1) nzb = ((const int*)mask)[widx] != 0;
            else               nzb = ((const float*)mask)[widx] != 0.0f;
            if (nzb) {
                b.e[ol * 9 + cnum] = make_int2(__float_as_int(w[widx]),
                                               (t / 3) * SMW2 + (t % 3));
                ++cnum;
            }
        }
        b.cnt[ol] = (unsigned char)cnum;
    }
}

// ---------------------------------------------------------------------------
// Pre-pad input to [N*IC][58][64] (row/col = input + 1, zeros at borders).
// ---------------------------------------------------------------------------
__global__ void prepad_kernel(const float* __restrict__ in) {
    size_t s = blockIdx.x;                 // n*CC + ic, 8192 slices
    const float* ip = in + s * (HW * HW);
    float* op = g_pad + s * (PADH * PADW);
    for (int idx = threadIdx.x; idx < PADH * PADW; idx += blockDim.x) {
        int r = idx >> 6;
        int c = idx & 63;
        int gy = r - 1, gx = c - 1;
        float v = 0.0f;
        if ((unsigned)gy < HW && (unsigned)gx < HW)
            v = ip[gy * HW + gx];
        op[idx] = v;
    }
}

// ---------------------------------------------------------------------------
// Main sparse conv, 2 images per CTA.
// Block = 16 warps; warp w owns oc = ot*16 + w over an 8x56 tile of BOTH images.
// Lane: q = lane>>2 (row), m = lane&3 (col phase); pixels cols m+4k, k=0..13.
// smem holds {img0,img1} interleaved per pixel -> per tap: 14 LDS.64 + 14 FFMA2.
// LDS.64 conflict-free: phase bank-pair = (4q+m) mod 16, all distinct.
// Staging: 1 ic/iter; thread jobs: input float2 (2x LDG.32) or metadata uint4,
// register-prefetched, double-buffered, ONE __syncthreads per iteration.
// ---------------------------------------------------------------------------
__global__ __launch_bounds__(THREADS, 2)
void sparse_conv_kernel(const float* __restrict__ bias,
                        float* __restrict__ out) {
    __shared__ __align__(16) unsigned char s_buf[2][ICB];

    const int tid  = threadIdx.x;
    const int wid  = tid >> 5;
    const int lane = tid & 31;
    const int ot   = blockIdx.x;       // fastest dim: 16 blocks share input in L2
    const int ty   = blockIdx.y;
    const int n0   = 2 * blockIdx.z;   // image pair
    const int row0 = ty * RT;
    const int oc   = ot * TOC + wid;

    // ---- staging job 1 (all threads): interleaved input float2, unit = tid
    int j1 = tid / 60, c1 = tid - 60 * j1;
    const float* s1 = g_pad + ((size_t)(n0 * CC) * PADH + row0 + j1) * PADW + c1;
    const int d1 = j1 * (SMW2 * 8) + c1 * 8;

    // ---- staging job 2: tid<88 -> input unit 512+tid; 88<=tid<161 -> metadata
    const int jobt = (tid < 88) ? 1 : (tid < 88 + MT_CHUNKS ? 2 : 0);
    const float* s2 = nullptr;
    const unsigned char* s2m = nullptr;
    int d2 = 0;
    if (jobt == 1) {
        int u = 512 + tid;
        int j2 = u / 60, c2 = u - 60 * j2;
        s2 = g_pad + ((size_t)(n0 * CC) * PADH + row0 + j2) * PADW + c2;
        d2 = j2 * (SMW2 * 8) + c2 * 8;
    } else if (jobt == 2) {
        s2m = (const unsigned char*)&g_buckets[ot * CC] + (tid - 88) * 16;
        d2 = CNT_OFF + (tid - 88) * 16;
    }

    // ---- accumulators: 14 packed f32x2 {img0, img1}
    const float bv = __ldg(&bias[oc]);
    const int bvi = __float_as_int(bv);
    unsigned long long acc[14];
#pragma unroll
    for (int k = 0; k < 14; ++k)
        asm("mov.b64 %0, {%1, %1};" : "=l"(acc[k]) : "r"(bvi));

    const int q = lane >> 2;
    const int m = lane & 3;
    const int rbase = q * SMW2 + m;

    // ---- prefetch first slice
    float a0 = __ldg(s1), a1 = __ldg(s1 + IMGSTRF);
    float b0 = 0.f, b1 = 0.f;
    uint4 mv = make_uint4(0, 0, 0, 0);
    if (jobt == 1)      { b0 = __ldg(s2); b1 = __ldg(s2 + IMGSTRF); }
    else if (jobt == 2) { mv = *(const uint4*)s2m; }

    for (int it = 0; it < CC; ++it) {
        unsigned char* buf = s_buf[it & 1];
        *(float2*)(buf + d1) = make_float2(a0, a1);
        if (jobt == 1)      *(float2*)(buf + d2) = make_float2(b0, b1);
        else if (jobt == 2) *(uint4*)(buf + d2)  = mv;

        if (it + 1 < CC) {                  // prefetch next ic (overlaps compute)
            s1 += SLICEF;
            a0 = __ldg(s1); a1 = __ldg(s1 + IMGSTRF);
            if (jobt == 1)      { s2 += SLICEF; b0 = __ldg(s2); b1 = __ldg(s2 + IMGSTRF); }
            else if (jobt == 2) { s2m += sizeof(GBucket); mv = *(const uint4*)s2m; }
        }
        __syncthreads();
        // single sync is safe: reads of buf[it&1] precede (in program order) the
        // sync at it+1, which precedes the next overwrite of this buffer at it+2.

        const unsigned char* blk = buf;
        const int cnt = blk[CNT_OFF + wid];                       // broadcast
        const int2* ep = (const int2*)(blk + ENT_OFF) + wid * 9;
        const float2* sp = (const float2*)blk + rbase;
        for (int t = 0; t < cnt; ++t) {
            int2 e = ep[t];                                       // broadcast
            unsigned long long w2;
            asm("mov.b64 %0, {%1, %1};" : "=l"(w2) : "r"(e.x));
            const float2* qp = sp + e.y;
#pragma unroll
            for (int k = 0; k < 14; ++k) {
                unsigned long long x = *(const unsigned long long*)(qp + 4 * k);
                asm("fma.rn.f32x2 %0, %1, %2, %0;" : "+l"(acc[k]) : "l"(x), "l"(w2));
            }
        }
    }

    const int gy = row0 + q;
    float* o0 = out + ((size_t)(n0 * CC + oc) * HW + gy) * HW + m;
    float* o1 = o0 + (size_t)CC * HW * HW;
#pragma unroll
    for (int k = 0; k < 14; ++k) {
        float2 f = *(float2*)&acc[k];
        o0[4 * k] = f.x;
        o1[4 * k] = f.y;
    }
}

// ---------------------------------------------------------------------------
extern "C" void kernel_launch(void* const* d_in, const int* in_sizes, int n_in,
                              void* d_out, int out_size) {
    const float* input  = (const float*)d_in[0];
    const float* weight = (const float*)d_in[1];
    const float* bias   = (const float*)d_in[2];
    const void*  mask   = d_in[3];
    float* out = (float*)d_out;

    detect_fmt_kernel<<<1, 256>>>((const unsigned char*)mask);
    build_buckets_kernel<<<16, 256>>>(weight, mask);
    prepad_kernel<<<NI * CC, 256>>>(input);
    sparse_conv_kernel<<<dim3(NOT, NTILE, NI / 2), THREADS>>>(bias, out);
}

// round 11
// speedup vs baseline: 1.0054x; 1.0020x over previous
#include <cuda_runtime.h>
#include <cuda_bf16.h>

// SparseConv2d: N=32, IC=OC=256, H=W=56, K=3, pad 1, ~90% zero weights. fp32 exact.
// R8: 2 images per CTA, interleaved {img0,img1} float2 smem tiles, packed
// fma.rn.f32x2 -> one LDS.64 feeds 2 px-FMAs. Halves instructions/FMA and CTA
// count; smem byte traffic (the 640us crossbar floor) unchanged.

#define NI      32
#define CC      256
#define HW      56
#define TOC     16          // ocs per block = warps per block
#define NOT     16          // 256 / TOC
#define RT      8           // output rows per tile
#define NTILE   7           // 56 / RT
#define SMW2    68          // smem row stride in float2 units (68%16==4 -> conflict-free)
#define PADW    64
#define PADH    58
#define THREADS 512

#define SLICEF  (PADH*PADW)      // floats per (n,ic) padded slice = 3712
#define IMGSTRF (CC*SLICEF)      // float offset img0 -> img1 = 950272

// per-ic smem block (bytes):
//   [0, 5440)      input: 10 rows * 68 float2 * 8B (cols 0..59 written)
//   [5440, 5456)   cnt[16]
//   [5456, 6608)   int2 e[16*9]
#define CNT_OFF 5440
#define ENT_OFF 5456
#define ICB     6608
#define IN_UNITS 600             // 10 rows * 60 cols, one interleaved float2 each
#define MT_CHUNKS 73             // sizeof(GBucket)/16

struct __align__(16) GBucket {
    unsigned char cnt[TOC];     // taps per local oc
    int2 e[TOC * 9];            // fixed stride 9: {w bits, delta = kh*SMW2 + kw}
};
static_assert(sizeof(GBucket) == 1168, "GBucket size");
static_assert(ENT_OFF + sizeof(GBucket) - 16 == ICB, "layout");

__device__ __align__(16) float g_pad[(size_t)NI * CC * PADH * PADW]; // ~121.6 MB scratch
__device__ GBucket g_buckets[NOT * CC];                              // ~4.8 MB
__device__ int     g_fmt;

// ---------------------------------------------------------------------------
// Mask dtype detection (bool/u8 vs int32 vs float32) by byte pattern.
// ---------------------------------------------------------------------------
__global__ void detect_fmt_kernel(const unsigned char* __restrict__ m) {
    __shared__ int nz[4];
    if (threadIdx.x < 4) nz[threadIdx.x] = 0;
    __syncthreads();
    for (int i = threadIdx.x; i < 4096; i += blockDim.x)
        if (m[i]) atomicOr(&nz[i & 3], 1);
    __syncthreads();
    if (threadIdx.x == 0) {
        int f;
        if (nz[1] | nz[2] | nz[3]) f = nz[0] ? 0 : 2;
        else                       f = 1;
        g_fmt = f;
    }
}

// ---------------------------------------------------------------------------
// Build per-(oc_tile, ic) tap lists, fixed 9-slot stride per oc.
// delta is in float2 units: kh*SMW2 + kw.
// ---------------------------------------------------------------------------
__global__ void build_buckets_kernel(const float* __restrict__ w,
                                     const void*  __restrict__ mask) {
    int bi = blockIdx.x * blockDim.x + threadIdx.x;
    if (bi >= NOT * CC) return;
    int ot = bi >> 8;
    int ic = bi & (CC - 1);
    int fmt = g_fmt;
    GBucket& b = g_buckets[bi];
    for (int ol = 0; ol < TOC; ++ol) {
        int oc = ot * TOC + ol;
        int base = (oc * CC + ic) * 9;
        int cnum = 0;
        for (int t = 0; t < 9; ++t) {
            int widx = base + t;
            bool nzb;
            if (fmt == 0)      nzb = ((const unsigned char*)mask)[widx] != 0;
            else if (fmt == 1) nzb = ((const int*)mask)[widx] != 0;
            else               nzb = ((const float*)mask)[widx] != 0.0f;
            if (nzb) {
                b.e[ol * 9 + cnum] = make_int2(__float_as_int(w[widx]),
                                               (t / 3) * SMW2 + (t % 3));
                ++cnum;
            }
        }
        b.cnt[ol] = (unsigned char)cnum;
    }
}

// ---------------------------------------------------------------------------
// Pre-pad input to [N*IC][58][64] (row/col = input + 1, zeros at borders).
// ---------------------------------------------------------------------------
__global__ void prepad_kernel(const float* __restrict__ in) {
    size_t s = blockIdx.x;                 // n*CC + ic, 8192 slices
    const float* ip = in + s * (HW * HW);
    float* op = g_pad + s * (PADH * PADW);
    for (int idx = threadIdx.x; idx < PADH * PADW; idx += blockDim.x) {
        int r = idx >> 6;
        int c = idx & 63;
        int gy = r - 1, gx = c - 1;
        float v = 0.0f;
        if ((unsigned)gy < HW && (unsigned)gx < HW)
            v = ip[gy * HW + gx];
        op[idx] = v;
    }
}

// ---------------------------------------------------------------------------
// Main sparse conv, 2 images per CTA.
// Block = 16 warps; warp w owns oc = ot*16 + w over an 8x56 tile of BOTH images.
// Lane: q = lane>>2 (row), m = lane&3 (col phase); pixels cols m+4k, k=0..13.
// smem holds {img0,img1} interleaved per pixel -> per tap: 14 LDS.64 + 14 FFMA2.
// LDS.64 conflict-free: phase bank-pair = (4q+m) mod 16, all distinct.
// Staging: 1 ic/iter; thread jobs: input float2 (2x LDG.32) or metadata uint4,
// register-prefetched, double-buffered, ONE __syncthreads per iteration.
// ---------------------------------------------------------------------------
__global__ __launch_bounds__(THREADS, 2)
void sparse_conv_kernel(const float* __restrict__ bias,
                        float* __restrict__ out) {
    __shared__ __align__(16) unsigned char s_buf[2][ICB];

    const int tid  = threadIdx.x;
    const int wid  = tid >> 5;
    const int lane = tid & 31;
    const int ot   = blockIdx.x;       // fastest dim: 16 blocks share input in L2
    const int ty   = blockIdx.y;
    const int n0   = 2 * blockIdx.z;   // image pair
    const int row0 = ty * RT;
    const int oc   = ot * TOC + wid;

    // ---- staging job 1 (all threads): interleaved input float2, unit = tid
    int j1 = tid / 60, c1 = tid - 60 * j1;
    const float* s1 = g_pad + ((size_t)(n0 * CC) * PADH + row0 + j1) * PADW + c1;
    const int d1 = j1 * (SMW2 * 8) + c1 * 8;

    // ---- staging job 2: tid<88 -> input unit 512+tid; 88<=tid<161 -> metadata
    const int jobt = (tid < 88) ? 1 : (tid < 88 + MT_CHUNKS ? 2 : 0);
    const float* s2 = nullptr;
    const unsigned char* s2m = nullptr;
    int d2 = 0;
    if (jobt == 1) {
        int u = 512 + tid;
        int j2 = u / 60, c2 = u - 60 * j2;
        s2 = g_pad + ((size_t)(n0 * CC) * PADH + row0 + j2) * PADW + c2;
        d2 = j2 * (SMW2 * 8) + c2 * 8;
    } else if (jobt == 2) {
        s2m = (const unsigned char*)&g_buckets[ot * CC] + (tid - 88) * 16;
        d2 = CNT_OFF + (tid - 88) * 16;
    }

    // ---- accumulators: 14 packed f32x2 {img0, img1}
    const float bv = __ldg(&bias[oc]);
    const int bvi = __float_as_int(bv);
    unsigned long long acc[14];
#pragma unroll
    for (int k = 0; k < 14; ++k)
        asm("mov.b64 %0, {%1, %1};" : "=l"(acc[k]) : "r"(bvi));

    const int q = lane >> 2;
    const int m = lane & 3;
    const int rbase = q * SMW2 + m;

    // ---- prefetch first slice
    float a0 = __ldg(s1), a1 = __ldg(s1 + IMGSTRF);
    float b0 = 0.f, b1 = 0.f;
    uint4 mv = make_uint4(0, 0, 0, 0);
    if (jobt == 1)      { b0 = __ldg(s2); b1 = __ldg(s2 + IMGSTRF); }
    else if (jobt == 2) { mv = *(const uint4*)s2m; }

    for (int it = 0; it < CC; ++it) {
        unsigned char* buf = s_buf[it & 1];
        *(float2*)(buf + d1) = make_float2(a0, a1);
        if (jobt == 1)      *(float2*)(buf + d2) = make_float2(b0, b1);
        else if (jobt == 2) *(uint4*)(buf + d2)  = mv;

        if (it + 1 < CC) {                  // prefetch next ic (overlaps compute)
            s1 += SLICEF;
            a0 = __ldg(s1); a1 = __ldg(s1 + IMGSTRF);
            if (jobt == 1)      { s2 += SLICEF; b0 = __ldg(s2); b1 = __ldg(s2 + IMGSTRF); }
            else if (jobt == 2) { s2m += sizeof(GBucket); mv = *(const uint4*)s2m; }
        }
        __syncthreads();
        // single sync is safe: reads of buf[it&1] precede (in program order) the
        // sync at it+1, which precedes the next overwrite of this buffer at it+2.

        const unsigned char* blk = buf;
        const int cnt = blk[CNT_OFF + wid];                       // broadcast
        const int2* ep = (const int2*)(blk + ENT_OFF) + wid * 9;
        const float2* sp = (const float2*)blk + rbase;
        for (int t = 0; t < cnt; ++t) {
            int2 e = ep[t];                                       // broadcast
            unsigned long long w2;
            asm("mov.b64 %0, {%1, %1};" : "=l"(w2) : "r"(e.x));
            const float2* qp = sp + e.y;
#pragma unroll
            for (int k = 0; k < 14; ++k) {
                unsigned long long x = *(const unsigned long long*)(qp + 4 * k);
                asm("fma.rn.f32x2 %0, %1, %2, %0;" : "+l"(acc[k]) : "l"(x), "l"(w2));
            }
        }
    }

    const int gy = row0 + q;
    float* o0 = out + ((size_t)(n0 * CC + oc) * HW + gy) * HW + m;
    float* o1 = o0 + (size_t)CC * HW * HW;
#pragma unroll
    for (int k = 0; k < 14; ++k) {
        float2 f = *(float2*)&acc[k];
        o0[4 * k] = f.x;
        o1[4 * k] = f.y;
    }
}

// ---------------------------------------------------------------------------
extern "C" void kernel_launch(void* const* d_in, const int* in_sizes, int n_in,
                              void* d_out, int out_size) {
    const float* input  = (const float*)d_in[0];
    const float* weight = (const float*)d_in[1];
    const float* bias   = (const float*)d_in[2];
    const void*  mask   = d_in[3];
    float* out = (float*)d_out;

    detect_fmt_kernel<<<1, 256>>>((const unsigned char*)mask);
    build_buckets_kernel<<<16, 256>>>(weight, mask);
    prepad_kernel<<<NI * CC, 256>>>(input);
    sparse_conv_kernel<<<dim3(NOT, NTILE, NI / 2), THREADS>>>(bias, out);
}